// round 5
// baseline (speedup 1.0000x reference)
#include <cuda_runtime.h>
#include <cuda_bf16.h>
#include <math.h>
#include <float.h>
#include <stdint.h>

#define TOKENS 8192
#define DIM 4096
#define NEXP 256
#define TOPK 8
#define TOPKG 4
#define ROUTE_SCALE 2.5f

// ---- static device scratch (no allocs allowed) ----
__device__ float g_logits[TOKENS * NEXP];                      // 8 MB
__device__ __nv_bfloat16 g_xh[TOKENS * DIM];                   // 64 MB
__device__ __nv_bfloat16 g_xm[TOKENS * DIM];
__device__ __nv_bfloat16 g_xl[TOKENS * DIM];
__device__ __nv_bfloat16 g_wh[NEXP * DIM];                     // 2 MB
__device__ __nv_bfloat16 g_wm[NEXP * DIM];
__device__ __nv_bfloat16 g_wl[NEXP * DIM];

// ===================== helpers =====================
__device__ __forceinline__ uint32_t smem_u32(const void* p) {
    uint32_t a;
    asm("{ .reg .u64 t; cvta.to.shared.u64 t, %1; cvt.u32.u64 %0, t; }" : "=r"(a) : "l"(p));
    return a;
}
__device__ __forceinline__ uint32_t packbf(float hi, float lo) {
    uint32_t r;
    asm("cvt.rn.bf16x2.f32 %0, %1, %2;" : "=r"(r) : "f"(hi), "f"(lo));
    return r;
}
__device__ __forceinline__ float unlo(uint32_t p) { return __uint_as_float(p << 16); }
__device__ __forceinline__ float unhi(uint32_t p) { return __uint_as_float(p & 0xffff0000u); }

__device__ __forceinline__ void cp_async16(uint32_t dst, const void* src) {
    asm volatile("cp.async.cg.shared.global [%0], [%1], 16;" :: "r"(dst), "l"(src) : "memory");
}
__device__ __forceinline__ void cp_commit() { asm volatile("cp.async.commit_group;" ::: "memory"); }
template <int N>
__device__ __forceinline__ void cp_wait() { asm volatile("cp.async.wait_group %0;" :: "n"(N) : "memory"); }

__device__ __forceinline__ void ldm_x4(uint32_t* r, uint32_t a) {
    asm volatile("ldmatrix.sync.aligned.m8n8.x4.shared.b16 {%0,%1,%2,%3}, [%4];"
        : "=r"(r[0]), "=r"(r[1]), "=r"(r[2]), "=r"(r[3]) : "r"(a));
}
__device__ __forceinline__ void ldm_x2(uint32_t* r, uint32_t a) {
    asm volatile("ldmatrix.sync.aligned.m8n8.x2.shared.b16 {%0,%1}, [%2];"
        : "=r"(r[0]), "=r"(r[1]) : "r"(a));
}
__device__ __forceinline__ void mma_bf16(float* c, const uint32_t* a, const uint32_t* b) {
    asm volatile(
        "mma.sync.aligned.m16n8k16.row.col.f32.bf16.bf16.f32 "
        "{%0,%1,%2,%3}, {%4,%5,%6,%7}, {%8,%9}, {%0,%1,%2,%3};"
        : "+f"(c[0]), "+f"(c[1]), "+f"(c[2]), "+f"(c[3])
        : "r"(a[0]), "r"(a[1]), "r"(a[2]), "r"(a[3]), "r"(b[0]), "r"(b[1]));
}

// ===================== split kernel: fp32 -> bf16 h/m/l (exact 3-way) =====================
__global__ __launch_bounds__(256)
void split_kernel(const float* __restrict__ src,
                  __nv_bfloat16* __restrict__ h,
                  __nv_bfloat16* __restrict__ m,
                  __nv_bfloat16* __restrict__ l, int n4) {
    int i = blockIdx.x * blockDim.x + threadIdx.x;
    if (i >= n4) return;
    float4 v = reinterpret_cast<const float4*>(src)[i];

    uint32_t hp0 = packbf(v.y, v.x);
    float r0 = v.x - unlo(hp0), r1 = v.y - unhi(hp0);
    uint32_t mp0 = packbf(r1, r0);
    float l0 = r0 - unlo(mp0), l1 = r1 - unhi(mp0);
    uint32_t lp0 = packbf(l1, l0);

    uint32_t hp1 = packbf(v.w, v.z);
    float r2 = v.z - unlo(hp1), r3 = v.w - unhi(hp1);
    uint32_t mp1 = packbf(r3, r2);
    float l2 = r2 - unlo(mp1), l3 = r3 - unhi(mp1);
    uint32_t lp1 = packbf(l3, l2);

    reinterpret_cast<uint2*>(h)[i] = make_uint2(hp0, hp1);
    reinterpret_cast<uint2*>(m)[i] = make_uint2(mp0, mp1);
    reinterpret_cast<uint2*>(l)[i] = make_uint2(lp0, lp1);
}

// ===================== GEMM: pure bf16 consumer, cp.async 3-stage =====================
// CTA tile 128x128, K chunk 32. smem/stage: 6 tiles [128 rows x 64B], stride 80B.
#define BKF 32
#define STRB 80
#define TILE_B (128 * STRB)        // 10240
#define STAGE_B (6 * TILE_B)       // 61440
#define NSTG 3
#define NCHUNK (DIM / BKF)         // 128
#define SMEM_TOTAL (NSTG * STAGE_B)  // 184320

__global__ __launch_bounds__(256, 1)
void gate_gemm_bf16x3(void) {
    extern __shared__ char smem[];
    const uint32_t sbm = smem_u32(smem);

    const int tid = threadIdx.x;
    const int wid = tid >> 5;
    const int lane = tid & 31;
    const int q = lane >> 2;
    const int t4 = lane & 3;
    const int wm = wid & 1;
    const int wn = wid >> 1;
    const int rowBase = blockIdx.y * 128;
    const int colBase = blockIdx.x * 128;

    // ---- cp.async source pointers: 12 x 16B segments per thread per chunk ----
    // segment i: comp = i>>1 (0..5 = xh,xm,xl,wh,wm,wl), row = (i&1)*64 + tid>>2, c = tid&3
    const __nv_bfloat16* srcs[6] = {g_xh, g_xm, g_xl, g_wh, g_wm, g_wl};
    const __nv_bfloat16* ptr[12];
    const int tr = tid >> 2, tc = tid & 3;
#pragma unroll
    for (int i = 0; i < 12; i++) {
        const int comp = i >> 1;
        const int base = (comp < 3 ? rowBase : colBase) + (i & 1) * 64 + tr;
        ptr[i] = srcs[comp] + (size_t)base * DIM + tc * 8;
    }

    // ---- consumer ldmatrix lane address bases ----
    const uint32_t aBase = (uint32_t)((wm * 64 + ((lane >> 3) & 1) * 8 + (lane & 7)) * STRB
                                      + (lane >> 4) * 16);
    const uint32_t bBase = (uint32_t)(3 * TILE_B + (wn * 32 + (lane & 7)) * STRB
                                      + ((lane >> 3) & 1) * 16);

    float accM[4][4][4];
    float accS[4][4][4];
#pragma unroll
    for (int mt = 0; mt < 4; mt++)
#pragma unroll
        for (int nt = 0; nt < 4; nt++)
#pragma unroll
            for (int e = 0; e < 4; e++) { accM[mt][nt][e] = 0.f; accS[mt][nt][e] = 0.f; }

    auto load_stage = [&](int g) {
        const uint32_t st = sbm + (uint32_t)(g % NSTG) * STAGE_B;
#pragma unroll
        for (int i = 0; i < 12; i++) {
            const uint32_t dst = st + (uint32_t)((i >> 1) * TILE_B + ((i & 1) * 64 + tr) * STRB + tc * 16);
            cp_async16(dst, ptr[i] + (size_t)g * BKF);
        }
    };

    load_stage(0); cp_commit();
    load_stage(1); cp_commit();

    for (int g = 0; g < NCHUNK; g++) {
        cp_wait<1>();
        __syncthreads();
        if (g + 2 < NCHUNK) load_stage(g + 2);
        cp_commit();

        const uint32_t stg = sbm + (uint32_t)(g % NSTG) * STAGE_B;
#pragma unroll
        for (int ks = 0; ks < 2; ks++) {
            const uint32_t kb2 = (uint32_t)(ks * 32);
            uint32_t Ah[4][4], Am[4][4], Al[4][4];
#pragma unroll
            for (int mt = 0; mt < 4; mt++) {
                const uint32_t a = stg + aBase + (uint32_t)(mt * 16 * STRB) + kb2;
                ldm_x4(Ah[mt], a);
                ldm_x4(Am[mt], a + TILE_B);
                ldm_x4(Al[mt], a + 2 * TILE_B);
            }
#pragma unroll
            for (int nt = 0; nt < 4; nt++) {
                const uint32_t b = stg + bBase + (uint32_t)(nt * 8 * STRB) + kb2;
                uint32_t Bh[2], Bm[2], Bl[2];
                ldm_x2(Bh, b);
                ldm_x2(Bm, b + TILE_B);
                ldm_x2(Bl, b + 2 * TILE_B);
#pragma unroll
                for (int mt = 0; mt < 4; mt++) {
                    mma_bf16(accM[mt][nt], Ah[mt], Bh);   // hh (isolated fp32 chain)
                    mma_bf16(accS[mt][nt], Ah[mt], Bm);   // hm
                    mma_bf16(accS[mt][nt], Am[mt], Bh);   // mh
                    mma_bf16(accS[mt][nt], Am[mt], Bm);   // mm
                    mma_bf16(accS[mt][nt], Ah[mt], Bl);   // hl
                    mma_bf16(accS[mt][nt], Al[mt], Bh);   // lh
                }
            }
        }
        __syncthreads();
    }

    // ---- epilogue ----
#pragma unroll
    for (int mt = 0; mt < 4; mt++) {
        const int row0 = rowBase + wm * 64 + mt * 16 + q;
#pragma unroll
        for (int nt = 0; nt < 4; nt++) {
            const int col = colBase + wn * 32 + nt * 8 + t4 * 2;
            float c0 = accM[mt][nt][0] + accS[mt][nt][0];
            float c1 = accM[mt][nt][1] + accS[mt][nt][1];
            float c2 = accM[mt][nt][2] + accS[mt][nt][2];
            float c3 = accM[mt][nt][3] + accS[mt][nt][3];
            *reinterpret_cast<float2*>(&g_logits[(size_t)row0 * NEXP + col]) = make_float2(c0, c1);
            *reinterpret_cast<float2*>(&g_logits[(size_t)(row0 + 8) * NEXP + col]) = make_float2(c2, c3);
        }
    }
}

// ===================== Routing: one warp per token =====================
__global__ __launch_bounds__(256)
void gate_route_kernel(const float* __restrict__ bias, float* __restrict__ out) {
    const int token = (blockIdx.x * blockDim.x + threadIdx.x) >> 5;
    const int lane = threadIdx.x & 31;
    if (token >= TOKENS) return;

    const float* lg = g_logits + (size_t)token * NEXP;
    const int ebase = lane * 8;

    float4 l0 = *reinterpret_cast<const float4*>(&lg[ebase]);
    float4 l1 = *reinterpret_cast<const float4*>(&lg[ebase + 4]);
    float4 bb0 = *reinterpret_cast<const float4*>(&bias[ebase]);
    float4 bb1 = *reinterpret_cast<const float4*>(&bias[ebase + 4]);

    float s[8], sb[8];
    {
        float lv[8] = {l0.x, l0.y, l0.z, l0.w, l1.x, l1.y, l1.z, l1.w};
        float bv[8] = {bb0.x, bb0.y, bb0.z, bb0.w, bb1.x, bb1.y, bb1.z, bb1.w};
#pragma unroll
        for (int j = 0; j < 8; j++) {
            s[j] = 1.0f / (1.0f + expf(-lv[j]));
            sb[j] = s[j] + bv[j];
        }
    }

    float t1 = -FLT_MAX, t2 = -FLT_MAX;
#pragma unroll
    for (int j = 0; j < 8; j++) {
        if (sb[j] > t1) { t2 = t1; t1 = sb[j]; }
        else if (sb[j] > t2) { t2 = sb[j]; }
    }
#pragma unroll
    for (int off = 1; off < 4; off <<= 1) {
        float o1 = __shfl_xor_sync(0xffffffffu, t1, off);
        float o2 = __shfl_xor_sync(0xffffffffu, t2, off);
        float n1 = fmaxf(t1, o1);
        float n2 = fmaxf(fminf(t1, o1), fmaxf(t2, o2));
        t1 = n1; t2 = n2;
    }
    float gscore = t1 + t2;
    int myg = lane >> 2;

    int rank = 0;
#pragma unroll
    for (int j = 0; j < 8; j++) {
        float gj = __shfl_sync(0xffffffffu, gscore, j * 4);
        rank += (gj > gscore) || (gj == gscore && j < myg);
    }
    bool gsel = rank < TOPKG;

    float v[8];
#pragma unroll
    for (int j = 0; j < 8; j++) v[j] = gsel ? sb[j] : 0.0f;

    int sel_idx = 0;
    float sel_s = 0.0f;
    float ssum = 0.0f;

#pragma unroll
    for (int r = 0; r < TOPK; r++) {
        float bv = -FLT_MAX, bs = 0.0f;
        int bidx = ebase;
#pragma unroll
        for (int j = 0; j < 8; j++) {
            if (v[j] > bv) { bv = v[j]; bidx = ebase + j; bs = s[j]; }
        }
#pragma unroll
        for (int off = 16; off > 0; off >>= 1) {
            float ov = __shfl_xor_sync(0xffffffffu, bv, off);
            int oi = __shfl_xor_sync(0xffffffffu, bidx, off);
            float os = __shfl_xor_sync(0xffffffffu, bs, off);
            if (ov > bv || (ov == bv && oi < bidx)) { bv = ov; bidx = oi; bs = os; }
        }
        if (lane == r) { sel_idx = bidx; sel_s = bs; }
        ssum += bs;
        if (lane == (bidx >> 3)) {
            int slot = bidx & 7;
#pragma unroll
            for (int j = 0; j < 8; j++)
                if (j == slot) v[j] = -FLT_MAX;
        }
    }

    if (lane < TOPK) {
        float w = sel_s / ssum * ROUTE_SCALE;
        out[(size_t)token * TOPK + lane] = w;
        out[(size_t)TOKENS * TOPK + (size_t)token * TOPK + lane] = (float)sel_idx;
    }
}

extern "C" void kernel_launch(void* const* d_in, const int* in_sizes, int n_in,
                              void* d_out, int out_size) {
    const float* x = (const float*)d_in[0];
    const float* W = (const float*)d_in[1];
    const float* bias = (const float*)d_in[2];
    float* out = (float*)d_out;

    __nv_bfloat16 *xh, *xm, *xl, *wh, *wmp, *wl;
    cudaGetSymbolAddress((void**)&xh, g_xh);
    cudaGetSymbolAddress((void**)&xm, g_xm);
    cudaGetSymbolAddress((void**)&xl, g_xl);
    cudaGetSymbolAddress((void**)&wh, g_wh);
    cudaGetSymbolAddress((void**)&wmp, g_wm);
    cudaGetSymbolAddress((void**)&wl, g_wl);

    split_kernel<<<(TOKENS * DIM / 4) / 256, 256>>>(x, xh, xm, xl, TOKENS * DIM / 4);
    split_kernel<<<(NEXP * DIM / 4) / 256, 256>>>(W, wh, wmp, wl, NEXP * DIM / 4);

    cudaFuncSetAttribute(gate_gemm_bf16x3, cudaFuncAttributeMaxDynamicSharedMemorySize, SMEM_TOTAL);
    dim3 grid(NEXP / 128, TOKENS / 128);
    gate_gemm_bf16x3<<<grid, 256, SMEM_TOTAL>>>();

    gate_route_kernel<<<TOKENS / 8, 256>>>(bias, out);
}

// round 7
// speedup vs baseline: 1.2009x; 1.2009x over previous
#include <cuda_runtime.h>
#include <cuda_bf16.h>
#include <math.h>
#include <float.h>
#include <stdint.h>

#define TOKENS 8192
#define DIM 4096
#define NEXP 256
#define TOPK 8
#define TOPKG 4
#define ROUTE_SCALE 2.5f

#define MTILE 64
#define BKF 32
#define NCHUNK (DIM / BKF)          // 128
#define STRB 80                     // bf16 tile row stride (bytes)
#define A_T (64 * STRB)             // 5120
#define B_T (256 * STRB)            // 20480
#define STAGE_B (3 * A_T + 3 * B_T) // 76800
#define SMEM_TOTAL (2 * STAGE_B)    // 153600
#define LSTR 260                    // logits smem row stride (floats), 16B-aligned rows

// ===================== helpers =====================
__device__ __forceinline__ uint32_t smem_u32(const void* p) {
    uint32_t a;
    asm("{ .reg .u64 t; cvta.to.shared.u64 t, %1; cvt.u32.u64 %0, t; }" : "=r"(a) : "l"(p));
    return a;
}
__device__ __forceinline__ uint32_t packbf(float hi, float lo) {
    uint32_t r;
    asm("cvt.rn.bf16x2.f32 %0, %1, %2;" : "=r"(r) : "f"(hi), "f"(lo));
    return r;
}
__device__ __forceinline__ float unlo(uint32_t p) { return __uint_as_float(p << 16); }
__device__ __forceinline__ float unhi(uint32_t p) { return __uint_as_float(p & 0xffff0000u); }

__device__ __forceinline__ void ldm_x4(uint32_t* r, uint32_t a) {
    asm volatile("ldmatrix.sync.aligned.m8n8.x4.shared.b16 {%0,%1,%2,%3}, [%4];"
        : "=r"(r[0]), "=r"(r[1]), "=r"(r[2]), "=r"(r[3]) : "r"(a));
}
__device__ __forceinline__ void ldm_x2(uint32_t* r, uint32_t a) {
    asm volatile("ldmatrix.sync.aligned.m8n8.x2.shared.b16 {%0,%1}, [%2];"
        : "=r"(r[0]), "=r"(r[1]) : "r"(a));
}
__device__ __forceinline__ void mma_bf16(float* c, const uint32_t* a, const uint32_t* b) {
    asm volatile(
        "mma.sync.aligned.m16n8k16.row.col.f32.bf16.bf16.f32 "
        "{%0,%1,%2,%3}, {%4,%5,%6,%7}, {%8,%9}, {%0,%1,%2,%3};"
        : "+f"(c[0]), "+f"(c[1]), "+f"(c[2]), "+f"(c[3])
        : "r"(a[0]), "r"(a[1]), "r"(a[2]), "r"(a[3]), "r"(b[0]), "r"(b[1]));
}
#define STS64(a, r0, r1) \
    asm volatile("st.shared.v2.b32 [%0], {%1, %2};" :: "r"(a), "r"(r0), "r"(r1) : "memory")

// ===================== fused kernel: GEMM(bf16x3) + group-limited top-k routing =====================
__global__ __launch_bounds__(256, 1)
void gate_fused(const float* __restrict__ x, const float* __restrict__ W,
                const float* __restrict__ bias, float* __restrict__ out) {
    extern __shared__ char smem[];
    const uint32_t sbm = smem_u32(smem);

    const int tid = threadIdx.x;
    const int wid = tid >> 5;
    const int lane = tid & 31;
    const int q = lane >> 2;
    const int t4 = lane & 3;
    const int wm = wid & 1;          // token half: rows wm*32
    const int wn = wid >> 1;         // expert quarter: cols wn*64
    const int rowBase = blockIdx.x * MTILE;

    // ---- producer mapping: 10 x float4 per thread per chunk (2 A-groups, 8 B-groups) ----
    const int pr = tid >> 3;         // 0..31
    const int pc = tid & 7;          // 16B segment
    const float* xsrc = x + (size_t)(rowBase + pr) * DIM + pc * 4;
    const float* wsrc = W + (size_t)pr * DIM + pc * 4;
    float4 pf[10];

    // ---- consumer ldmatrix bases ----
    const uint32_t aBase = (uint32_t)((wm * 32 + ((lane >> 3) & 1) * 8 + (lane & 7)) * STRB
                                      + (lane >> 4) * 16);
    const uint32_t bBase = (uint32_t)(3 * A_T + (wn * 64 + (lane & 7)) * STRB
                                      + ((lane >> 3) & 1) * 16);

    float accM[2][8][4];
    float accS[2][8][4];
#pragma unroll
    for (int mt = 0; mt < 2; mt++)
#pragma unroll
        for (int nt = 0; nt < 8; nt++)
#pragma unroll
            for (int e = 0; e < 4; e++) { accM[mt][nt][e] = 0.f; accS[mt][nt][e] = 0.f; }

    auto ldg_chunk = [&](int g) {
#pragma unroll
        for (int j = 0; j < 2; j++)
            pf[j] = *reinterpret_cast<const float4*>(xsrc + (size_t)j * 32 * DIM + (size_t)g * BKF);
#pragma unroll
        for (int j = 2; j < 10; j++)
            pf[j] = *reinterpret_cast<const float4*>(wsrc + (size_t)(j - 2) * 32 * DIM + (size_t)g * BKF);
    };

    auto produce = [&](int s) {
        const uint32_t base = sbm + (uint32_t)s * STAGE_B;
#pragma unroll
        for (int j = 0; j < 10; j++) {
            const float4 v = pf[j];
            uint32_t hp0 = packbf(v.y, v.x);
            float r0 = v.x - unlo(hp0), r1 = v.y - unhi(hp0);
            uint32_t mp0 = packbf(r1, r0);
            float l0 = r0 - unlo(mp0), l1 = r1 - unhi(mp0);
            uint32_t lp0 = packbf(l1, l0);

            uint32_t hp1 = packbf(v.w, v.z);
            float r2 = v.z - unlo(hp1), r3 = v.w - unhi(hp1);
            uint32_t mp1 = packbf(r3, r2);
            float l2 = r2 - unlo(mp1), l3 = r3 - unhi(mp1);
            uint32_t lp1 = packbf(l3, l2);

            uint32_t addr;
            uint32_t tstep;
            if (j < 2) {
                addr = base + (uint32_t)((j * 32 + pr) * STRB + pc * 8);
                tstep = A_T;
            } else {
                addr = base + (uint32_t)(3 * A_T + ((j - 2) * 32 + pr) * STRB + pc * 8);
                tstep = B_T;
            }
            STS64(addr, hp0, hp1);
            STS64(addr + tstep, mp0, mp1);
            STS64(addr + 2 * tstep, lp0, lp1);
        }
    };

    // prologue
    ldg_chunk(0);
    produce(0);
    __syncthreads();

    for (int g = 0; g < NCHUNK; g++) {
        if (g + 1 < NCHUNK) ldg_chunk(g + 1);

        const uint32_t stg = sbm + (uint32_t)(g & 1) * STAGE_B;
#pragma unroll
        for (int ks = 0; ks < 2; ks++) {
            const uint32_t kb2 = (uint32_t)(ks * 32);
            uint32_t Ah[2][4], Am[2][4], Al[2][4];
#pragma unroll
            for (int mt = 0; mt < 2; mt++) {
                const uint32_t a = stg + aBase + (uint32_t)(mt * 16 * STRB) + kb2;
                ldm_x4(Ah[mt], a);
                ldm_x4(Am[mt], a + A_T);
                ldm_x4(Al[mt], a + 2 * A_T);
            }
#pragma unroll
            for (int nt = 0; nt < 8; nt++) {
                const uint32_t b = stg + bBase + (uint32_t)(nt * 8 * STRB) + kb2;
                uint32_t Bh[2], Bm[2], Bl[2];
                ldm_x2(Bh, b);
                ldm_x2(Bm, b + B_T);
                ldm_x2(Bl, b + 2 * B_T);
#pragma unroll
                for (int mt = 0; mt < 2; mt++) {
                    mma_bf16(accM[mt][nt], Ah[mt], Bh);   // hh (isolated fp32 chain)
                    mma_bf16(accS[mt][nt], Ah[mt], Bm);   // hm
                    mma_bf16(accS[mt][nt], Am[mt], Bh);   // mh
                    mma_bf16(accS[mt][nt], Am[mt], Bm);   // mm
                    mma_bf16(accS[mt][nt], Ah[mt], Bl);   // hl
                    mma_bf16(accS[mt][nt], Al[mt], Bh);   // lh
                }
            }
        }

        if (g + 1 < NCHUNK) produce((g + 1) & 1);
        __syncthreads();
    }

    // ---- epilogue: logits into smem [64 tokens x 256 experts], stride LSTR ----
    float* lgs = reinterpret_cast<float*>(smem);
#pragma unroll
    for (int mt = 0; mt < 2; mt++) {
        const int row = wm * 32 + mt * 16 + q;
#pragma unroll
        for (int nt = 0; nt < 8; nt++) {
            const int col = wn * 64 + nt * 8 + t4 * 2;
            float c0 = accM[mt][nt][0] + accS[mt][nt][0];
            float c1 = accM[mt][nt][1] + accS[mt][nt][1];
            float c2 = accM[mt][nt][2] + accS[mt][nt][2];
            float c3 = accM[mt][nt][3] + accS[mt][nt][3];
            *reinterpret_cast<float2*>(&lgs[row * LSTR + col]) = make_float2(c0, c1);
            *reinterpret_cast<float2*>(&lgs[(row + 8) * LSTR + col]) = make_float2(c2, c3);
        }
    }
    __syncthreads();

    // ---- fused routing: each warp routes 8 tokens; lane owns experts [lane*8, lane*8+8) ----
    const int ebase = lane * 8;
    const float4 bb0 = *reinterpret_cast<const float4*>(&bias[ebase]);
    const float4 bb1 = *reinterpret_cast<const float4*>(&bias[ebase + 4]);

    for (int it = 0; it < 8; it++) {
        const int tloc = wid * 8 + it;
        const int token = rowBase + tloc;

        float4 l0 = *reinterpret_cast<const float4*>(&lgs[tloc * LSTR + ebase]);
        float4 l1 = *reinterpret_cast<const float4*>(&lgs[tloc * LSTR + ebase + 4]);

        float s[8], sb[8];
        {
            float lv[8] = {l0.x, l0.y, l0.z, l0.w, l1.x, l1.y, l1.z, l1.w};
            float bv[8] = {bb0.x, bb0.y, bb0.z, bb0.w, bb1.x, bb1.y, bb1.z, bb1.w};
#pragma unroll
            for (int j = 0; j < 8; j++) {
                s[j] = 1.0f / (1.0f + expf(-lv[j]));
                sb[j] = s[j] + bv[j];
            }
        }

        // group top-2 (groups of 32 experts = 4 lanes)
        float t1 = -FLT_MAX, t2 = -FLT_MAX;
#pragma unroll
        for (int j = 0; j < 8; j++) {
            if (sb[j] > t1) { t2 = t1; t1 = sb[j]; }
            else if (sb[j] > t2) { t2 = sb[j]; }
        }
#pragma unroll
        for (int off = 1; off < 4; off <<= 1) {
            float o1 = __shfl_xor_sync(0xffffffffu, t1, off);
            float o2 = __shfl_xor_sync(0xffffffffu, t2, off);
            float n1 = fmaxf(t1, o1);
            float n2 = fmaxf(fminf(t1, o1), fmaxf(t2, o2));
            t1 = n1; t2 = n2;
        }
        float gscore = t1 + t2;
        int myg = lane >> 2;

        int rank = 0;
#pragma unroll
        for (int j = 0; j < 8; j++) {
            float gj = __shfl_sync(0xffffffffu, gscore, j * 4);
            rank += (gj > gscore) || (gj == gscore && j < myg);
        }
        bool gsel = rank < TOPKG;

        float v[8];
#pragma unroll
        for (int j = 0; j < 8; j++) v[j] = gsel ? sb[j] : 0.0f;

        int sel_idx = 0;
        float sel_s = 0.0f;
        float ssum = 0.0f;

#pragma unroll
        for (int r = 0; r < TOPK; r++) {
            float bv = -FLT_MAX, bs = 0.0f;
            int bidx = ebase;
#pragma unroll
            for (int j = 0; j < 8; j++) {
                if (v[j] > bv) { bv = v[j]; bidx = ebase + j; bs = s[j]; }
            }
#pragma unroll
            for (int off = 16; off > 0; off >>= 1) {
                float ov = __shfl_xor_sync(0xffffffffu, bv, off);
                int oi = __shfl_xor_sync(0xffffffffu, bidx, off);
                float os = __shfl_xor_sync(0xffffffffu, bs, off);
                if (ov > bv || (ov == bv && oi < bidx)) { bv = ov; bidx = oi; bs = os; }
            }
            if (lane == r) { sel_idx = bidx; sel_s = bs; }
            ssum += bs;
            if (lane == (bidx >> 3)) {
                int slot = bidx & 7;
#pragma unroll
                for (int j = 0; j < 8; j++)
                    if (j == slot) v[j] = -FLT_MAX;
            }
        }

        if (lane < TOPK) {
            float w = sel_s / ssum * ROUTE_SCALE;
            out[(size_t)token * TOPK + lane] = w;
            out[(size_t)TOKENS * TOPK + (size_t)token * TOPK + lane] = (float)sel_idx;
        }
    }
}

extern "C" void kernel_launch(void* const* d_in, const int* in_sizes, int n_in,
                              void* d_out, int out_size) {
    const float* x = (const float*)d_in[0];
    const float* W = (const float*)d_in[1];
    const float* bias = (const float*)d_in[2];
    float* out = (float*)d_out;

    cudaFuncSetAttribute(gate_fused, cudaFuncAttributeMaxDynamicSharedMemorySize, SMEM_TOTAL);
    gate_fused<<<TOKENS / MTILE, 256, SMEM_TOTAL>>>(x, W, bias, out);
}

// round 10
// speedup vs baseline: 1.2428x; 1.0349x over previous
#include <cuda_runtime.h>
#include <cuda_bf16.h>
#include <math.h>
#include <float.h>
#include <stdint.h>

#define TOKENS 8192
#define DIM 4096
#define NEXP 256
#define TOPK 8
#define TOPKG 4
#define ROUTE_SCALE 2.5f

#define MTILE 64
#define BKF 32
#define NCHUNK (DIM / BKF)          // 128
#define STRB 80                     // bf16 tile row stride (bytes)
#define A_T (64 * STRB)             // 5120
#define B_T (256 * STRB)            // 20480
#define STAGE_B (3 * A_T + 3 * B_T) // 76800
#define SMEM_TOTAL (2 * STAGE_B)    // 153600
#define LSTR 260                    // logits smem row stride (floats)

#define NTHREADS 384                // 8 consumer warps + 4 producer warps

// named barrier ids: 1,2 = full(stage), 3,4 = empty(stage), 5 = consumer epilogue
#define BAR_SYNC(id, cnt)   asm volatile("bar.sync %0, %1;"   :: "r"(id), "r"(cnt) : "memory")
#define BAR_ARRIVE(id, cnt) asm volatile("bar.arrive %0, %1;" :: "r"(id), "r"(cnt) : "memory")

// ===================== helpers =====================
__device__ __forceinline__ uint32_t smem_u32(const void* p) {
    uint32_t a;
    asm("{ .reg .u64 t; cvta.to.shared.u64 t, %1; cvt.u32.u64 %0, t; }" : "=r"(a) : "l"(p));
    return a;
}
__device__ __forceinline__ uint32_t packbf(float hi, float lo) {
    uint32_t r;
    asm("cvt.rn.bf16x2.f32 %0, %1, %2;" : "=r"(r) : "f"(hi), "f"(lo));
    return r;
}
__device__ __forceinline__ float unlo(uint32_t p) { return __uint_as_float(p << 16); }
__device__ __forceinline__ float unhi(uint32_t p) { return __uint_as_float(p & 0xffff0000u); }

__device__ __forceinline__ void ldm_x4(uint32_t* r, uint32_t a) {
    asm volatile("ldmatrix.sync.aligned.m8n8.x4.shared.b16 {%0,%1,%2,%3}, [%4];"
        : "=r"(r[0]), "=r"(r[1]), "=r"(r[2]), "=r"(r[3]) : "r"(a));
}
__device__ __forceinline__ void ldm_x2(uint32_t* r, uint32_t a) {
    asm volatile("ldmatrix.sync.aligned.m8n8.x2.shared.b16 {%0,%1}, [%2];"
        : "=r"(r[0]), "=r"(r[1]) : "r"(a));
}
__device__ __forceinline__ void mma_bf16(float* c, const uint32_t* a, const uint32_t* b) {
    asm volatile(
        "mma.sync.aligned.m16n8k16.row.col.f32.bf16.bf16.f32 "
        "{%0,%1,%2,%3}, {%4,%5,%6,%7}, {%8,%9}, {%0,%1,%2,%3};"
        : "+f"(c[0]), "+f"(c[1]), "+f"(c[2]), "+f"(c[3])
        : "r"(a[0]), "r"(a[1]), "r"(a[2]), "r"(a[3]), "r"(b[0]), "r"(b[1]));
}
#define STS64(a, r0, r1) \
    asm volatile("st.shared.v2.b32 [%0], {%1, %2};" :: "r"(a), "r"(r0), "r"(r1) : "memory")

// split one float4 into 3 bf16x2 pairs and store at (addr, addr+tstep, addr+2*tstep)
__device__ __forceinline__ void split_store(float4 v, uint32_t addr, uint32_t tstep) {
    uint32_t hp0 = packbf(v.y, v.x);
    float r0 = v.x - unlo(hp0), r1 = v.y - unhi(hp0);
    uint32_t mp0 = packbf(r1, r0);
    float l0 = r0 - unlo(mp0), l1 = r1 - unhi(mp0);
    uint32_t lp0 = packbf(l1, l0);

    uint32_t hp1 = packbf(v.w, v.z);
    float r2 = v.z - unlo(hp1), r3 = v.w - unhi(hp1);
    uint32_t mp1 = packbf(r3, r2);
    float l2 = r2 - unlo(mp1), l3 = r3 - unhi(mp1);
    uint32_t lp1 = packbf(l3, l2);

    STS64(addr, hp0, hp1);
    STS64(addr + tstep, mp0, mp1);
    STS64(addr + 2 * tstep, lp0, lp1);
}

// ===================== fused WS kernel =====================
__global__ __launch_bounds__(NTHREADS, 1)
void gate_fused_ws(const float* __restrict__ x, const float* __restrict__ W,
                   const float* __restrict__ bias, float* __restrict__ out) {
    extern __shared__ char smem[];
    const uint32_t sbm = smem_u32(smem);

    const int tid = threadIdx.x;
    const int wid = tid >> 5;
    const int lane = tid & 31;
    const int rowBase = blockIdx.x * MTILE;

    if (wid >= 8) {
        // ================= PRODUCER (warps 8-11, 128 threads) =================
        const int pt = tid - 256;           // 0..127
        // A: 512 segments (64 rows x 8), 4 per thread; B: 2048 segments, 16 per thread
        float4 pfA[4], pfB[16];
        const float* xs = x;
        const float* ws = W;

        for (int g = 0; g < NCHUNK; g++) {
            const int s = g & 1;
            const size_t kof = (size_t)g * BKF;
            // prefetch (gmem loads don't touch smem; safe before empty-wait)
#pragma unroll
            for (int i = 0; i < 4; i++) {
                const int seg = pt + i * 128;
                pfA[i] = *reinterpret_cast<const float4*>(
                    xs + (size_t)(rowBase + (seg >> 3)) * DIM + kof + (seg & 7) * 4);
            }
#pragma unroll
            for (int i = 0; i < 16; i++) {
                const int seg = pt + i * 128;
                pfB[i] = *reinterpret_cast<const float4*>(
                    ws + (size_t)(seg >> 3) * DIM + kof + (seg & 7) * 4);
            }

            if (g >= 2) BAR_SYNC(3 + s, NTHREADS);       // wait empty(stage s)

            const uint32_t stage = sbm + (uint32_t)s * STAGE_B;
#pragma unroll
            for (int i = 0; i < 4; i++) {
                const int seg = pt + i * 128;
                split_store(pfA[i], stage + (uint32_t)((seg >> 3) * STRB + (seg & 7) * 8), A_T);
            }
#pragma unroll
            for (int i = 0; i < 16; i++) {
                const int seg = pt + i * 128;
                split_store(pfB[i],
                            stage + (uint32_t)(3 * A_T + (seg >> 3) * STRB + (seg & 7) * 8), B_T);
            }
            BAR_ARRIVE(1 + s, NTHREADS);                 // signal full(stage s)
        }
        return;   // producers exit; routing handled by consumers
    }

    // ================= CONSUMER (warps 0-7, 256 threads) =================
    const int q = lane >> 2;
    const int t4 = lane & 3;
    const int wm = wid & 1;          // token half: rows wm*32
    const int wn = wid >> 1;         // expert quarter: cols wn*64

    const uint32_t aBase = (uint32_t)((wm * 32 + ((lane >> 3) & 1) * 8 + (lane & 7)) * STRB
                                      + (lane >> 4) * 16);
    const uint32_t bBase = (uint32_t)(3 * A_T + (wn * 64 + (lane & 7)) * STRB
                                      + ((lane >> 3) & 1) * 16);

    float accM[2][8][4];
    float accS[2][8][4];
#pragma unroll
    for (int mt = 0; mt < 2; mt++)
#pragma unroll
        for (int nt = 0; nt < 8; nt++)
#pragma unroll
            for (int e = 0; e < 4; e++) { accM[mt][nt][e] = 0.f; accS[mt][nt][e] = 0.f; }

    for (int g = 0; g < NCHUNK; g++) {
        const int s = g & 1;
        BAR_SYNC(1 + s, NTHREADS);                       // wait full(stage s)

        const uint32_t stg = sbm + (uint32_t)s * STAGE_B;
#pragma unroll
        for (int ks = 0; ks < 2; ks++) {
            const uint32_t kb2 = (uint32_t)(ks * 32);
            uint32_t Ah[2][4], Am[2][4], Al[2][4];
#pragma unroll
            for (int mt = 0; mt < 2; mt++) {
                const uint32_t a = stg + aBase + (uint32_t)(mt * 16 * STRB) + kb2;
                ldm_x4(Ah[mt], a);
                ldm_x4(Am[mt], a + A_T);
                ldm_x4(Al[mt], a + 2 * A_T);
            }
#pragma unroll
            for (int nt = 0; nt < 8; nt++) {
                const uint32_t b = stg + bBase + (uint32_t)(nt * 8 * STRB) + kb2;
                uint32_t Bh[2], Bm[2], Bl[2];
                ldm_x2(Bh, b);
                ldm_x2(Bm, b + B_T);
                ldm_x2(Bl, b + 2 * B_T);
#pragma unroll
                for (int mt = 0; mt < 2; mt++) {
                    mma_bf16(accM[mt][nt], Ah[mt], Bh);   // hh (isolated fp32 chain)
                    mma_bf16(accS[mt][nt], Ah[mt], Bm);   // hm
                    mma_bf16(accS[mt][nt], Am[mt], Bh);   // mh
                    mma_bf16(accS[mt][nt], Am[mt], Bm);   // mm
                    mma_bf16(accS[mt][nt], Ah[mt], Bl);   // hl
                    mma_bf16(accS[mt][nt], Al[mt], Bh);   // lh
                }
            }
        }
        BAR_ARRIVE(3 + s, NTHREADS);                     // signal empty(stage s)
    }

    // ---- epilogue: logits into smem [64 x 256], stride LSTR ----
    float* lgs = reinterpret_cast<float*>(smem);
#pragma unroll
    for (int mt = 0; mt < 2; mt++) {
        const int row = wm * 32 + mt * 16 + q;
#pragma unroll
        for (int nt = 0; nt < 8; nt++) {
            const int col = wn * 64 + nt * 8 + t4 * 2;
            float c0 = accM[mt][nt][0] + accS[mt][nt][0];
            float c1 = accM[mt][nt][1] + accS[mt][nt][1];
            float c2 = accM[mt][nt][2] + accS[mt][nt][2];
            float c3 = accM[mt][nt][3] + accS[mt][nt][3];
            *reinterpret_cast<float2*>(&lgs[row * LSTR + col]) = make_float2(c0, c1);
            *reinterpret_cast<float2*>(&lgs[(row + 8) * LSTR + col]) = make_float2(c2, c3);
        }
    }
    BAR_SYNC(5, 256);   // consumer-only barrier: lgs fully written

    // ---- routing: each consumer warp routes 8 tokens; lane owns 8 experts ----
    const int ebase = lane * 8;
    const float4 bb0 = *reinterpret_cast<const float4*>(&bias[ebase]);
    const float4 bb1 = *reinterpret_cast<const float4*>(&bias[ebase + 4]);

    for (int it = 0; it < 8; it++) {
        const int tloc = wid * 8 + it;
        const int token = rowBase + tloc;

        float4 l0 = *reinterpret_cast<const float4*>(&lgs[tloc * LSTR + ebase]);
        float4 l1 = *reinterpret_cast<const float4*>(&lgs[tloc * LSTR + ebase + 4]);

        float s[8], sb[8];
        {
            float lv[8] = {l0.x, l0.y, l0.z, l0.w, l1.x, l1.y, l1.z, l1.w};
            float bv[8] = {bb0.x, bb0.y, bb0.z, bb0.w, bb1.x, bb1.y, bb1.z, bb1.w};
#pragma unroll
            for (int j = 0; j < 8; j++) {
                s[j] = 1.0f / (1.0f + expf(-lv[j]));
                sb[j] = s[j] + bv[j];
            }
        }

        float t1 = -FLT_MAX, t2 = -FLT_MAX;
#pragma unroll
        for (int j = 0; j < 8; j++) {
            if (sb[j] > t1) { t2 = t1; t1 = sb[j]; }
            else if (sb[j] > t2) { t2 = sb[j]; }
        }
#pragma unroll
        for (int off = 1; off < 4; off <<= 1) {
            float o1 = __shfl_xor_sync(0xffffffffu, t1, off);
            float o2 = __shfl_xor_sync(0xffffffffu, t2, off);
            float n1 = fmaxf(t1, o1);
            float n2 = fmaxf(fminf(t1, o1), fmaxf(t2, o2));
            t1 = n1; t2 = n2;
        }
        float gscore = t1 + t2;
        int myg = lane >> 2;

        int rank = 0;
#pragma unroll
        for (int j = 0; j < 8; j++) {
            float gj = __shfl_sync(0xffffffffu, gscore, j * 4);
            rank += (gj > gscore) || (gj == gscore && j < myg);
        }
        bool gsel = rank < TOPKG;

        float v[8];
#pragma unroll
        for (int j = 0; j < 8; j++) v[j] = gsel ? sb[j] : 0.0f;

        int sel_idx = 0;
        float sel_s = 0.0f;
        float ssum = 0.0f;

#pragma unroll
        for (int r = 0; r < TOPK; r++) {
            float bv = -FLT_MAX, bs = 0.0f;
            int bidx = ebase;
#pragma unroll
            for (int j = 0; j < 8; j++) {
                if (v[j] > bv) { bv = v[j]; bidx = ebase + j; bs = s[j]; }
            }
#pragma unroll
            for (int off = 16; off > 0; off >>= 1) {
                float ov = __shfl_xor_sync(0xffffffffu, bv, off);
                int oi = __shfl_xor_sync(0xffffffffu, bidx, off);
                float os = __shfl_xor_sync(0xffffffffu, bs, off);
                if (ov > bv || (ov == bv && oi < bidx)) { bv = ov; bidx = oi; bs = os; }
            }
            if (lane == r) { sel_idx = bidx; sel_s = bs; }
            ssum += bs;
            if (lane == (bidx >> 3)) {
                int slot = bidx & 7;
#pragma unroll
                for (int j = 0; j < 8; j++)
                    if (j == slot) v[j] = -FLT_MAX;
            }
        }

        if (lane < TOPK) {
            float w = sel_s / ssum * ROUTE_SCALE;
            out[(size_t)token * TOPK + lane] = w;
            out[(size_t)TOKENS * TOPK + (size_t)token * TOPK + lane] = (float)sel_idx;
        }
    }
}

extern "C" void kernel_launch(void* const* d_in, const int* in_sizes, int n_in,
                              void* d_out, int out_size) {
    const float* x = (const float*)d_in[0];
    const float* W = (const float*)d_in[1];
    const float* bias = (const float*)d_in[2];
    float* out = (float*)d_out;

    cudaFuncSetAttribute(gate_fused_ws, cudaFuncAttributeMaxDynamicSharedMemorySize, SMEM_TOTAL);
    gate_fused_ws<<<TOKENS / MTILE, NTHREADS, SMEM_TOTAL>>>(x, W, bias, out);
}

// round 15
// speedup vs baseline: 1.2517x; 1.0071x over previous
#include <cuda_runtime.h>
#include <cuda_fp16.h>
#include <math.h>
#include <float.h>
#include <stdint.h>

#define TOKENS 8192
#define DIM 4096
#define NEXP 256
#define TOPK 8
#define TOPKG 4
#define ROUTE_SCALE 2.5f
#define WSCALE 64.0f
#define INV_WSCALE 0.015625f

#define MTILE 64
#define BKF 32
#define NCHUNK (DIM / BKF)          // 128
#define STRB 80                     // fp16 tile row stride (bytes): 32*2=64B data + pad
#define A_T (64 * STRB)             // 5120
#define B_T (256 * STRB)            // 20480
#define STAGE_B (2 * A_T + 2 * B_T) // 51200  (Ah, Am, Bh, Bm)
#define SMEM_TOTAL (2 * STAGE_B)    // 102400
#define LSTR 260                    // logits smem row stride (floats)

// ===================== helpers =====================
__device__ __forceinline__ uint32_t smem_u32(const void* p) {
    uint32_t a;
    asm("{ .reg .u64 t; cvta.to.shared.u64 t, %1; cvt.u32.u64 %0, t; }" : "=r"(a) : "l"(p));
    return a;
}
__device__ __forceinline__ void ldm_x4(uint32_t* r, uint32_t a) {
    asm volatile("ldmatrix.sync.aligned.m8n8.x4.shared.b16 {%0,%1,%2,%3}, [%4];"
        : "=r"(r[0]), "=r"(r[1]), "=r"(r[2]), "=r"(r[3]) : "r"(a));
}
__device__ __forceinline__ void mma_f16(float* c, const uint32_t* a, const uint32_t* b) {
    asm volatile(
        "mma.sync.aligned.m16n8k16.row.col.f32.f16.f16.f32 "
        "{%0,%1,%2,%3}, {%4,%5,%6,%7}, {%8,%9}, {%0,%1,%2,%3};"
        : "+f"(c[0]), "+f"(c[1]), "+f"(c[2]), "+f"(c[3])
        : "r"(a[0]), "r"(a[1]), "r"(a[2]), "r"(a[3]), "r"(b[0]), "r"(b[1]));
}
#define STS64(a, r0, r1) \
    asm volatile("st.shared.v2.b32 [%0], {%1, %2};" :: "r"(a), "r"(r0), "r"(r1) : "memory")

__device__ __forceinline__ uint32_t packh2(__half lo, __half hi) {
    __half2 h = __halves2half2(lo, hi);
    return *reinterpret_cast<uint32_t*>(&h);
}

// fp16 2-way split of one float4 -> store h pair + m pair
__device__ __forceinline__ void split_store2(float4 v, uint32_t addr, uint32_t tstep) {
    __half h0 = __float2half_rn(v.x), h1 = __float2half_rn(v.y);
    __half h2 = __float2half_rn(v.z), h3 = __float2half_rn(v.w);
    float r0 = v.x - __half2float(h0), r1 = v.y - __half2float(h1);
    float r2 = v.z - __half2float(h2), r3 = v.w - __half2float(h3);
    __half m0 = __float2half_rn(r0), m1 = __float2half_rn(r1);
    __half m2 = __float2half_rn(r2), m3 = __float2half_rn(r3);
    STS64(addr, packh2(h0, h1), packh2(h2, h3));
    STS64(addr + tstep, packh2(m0, m1), packh2(m2, m3));
}

// ===================== fused kernel: GEMM(fp16x2, 4 terms) + routing =====================
__global__ __launch_bounds__(256, 1)
void gate_fused(const float* __restrict__ x, const float* __restrict__ W,
                const float* __restrict__ bias, float* __restrict__ out) {
    extern __shared__ char smem[];
    const uint32_t sbm = smem_u32(smem);

    const int tid = threadIdx.x;
    const int wid = tid >> 5;
    const int lane = tid & 31;
    const int q = lane >> 2;
    const int t4 = lane & 3;
    const int wm = wid & 1;          // token half: rows wm*32
    const int wn = wid >> 1;         // expert quarter: cols wn*64
    const int rowBase = blockIdx.x * MTILE;

    // ---- producer mapping: 10 x float4 per thread per chunk (2 A, 8 B) ----
    const int pr = tid >> 3;         // 0..31 row-in-group
    const int pc = tid & 7;          // 16B segment
    const float* xsrc = x + (size_t)(rowBase + pr) * DIM + pc * 4;
    const float* wsrc = W + (size_t)pr * DIM + pc * 4;
    float4 pf[10];

    // ---- consumer ldmatrix bases ----
    // A x4: 16 rows x 32B fragment
    const uint32_t aBase = (uint32_t)((wm * 32 + ((lane >> 3) & 1) * 8 + (lane & 7)) * STRB
                                      + (lane >> 4) * 16);
    // B x4: 16 n-rows x 32B (two mma B-frags): rows (lane&7) + (lane>>4)*8, k-off ((lane>>3)&1)*16
    const uint32_t bBase = (uint32_t)(2 * A_T
                                      + (wn * 64 + (lane & 7) + (lane >> 4) * 8) * STRB
                                      + ((lane >> 3) & 1) * 16);

    float accM[2][8][4];
    float accS[2][8][4];
#pragma unroll
    for (int mt = 0; mt < 2; mt++)
#pragma unroll
        for (int nt = 0; nt < 8; nt++)
#pragma unroll
            for (int e = 0; e < 4; e++) { accM[mt][nt][e] = 0.f; accS[mt][nt][e] = 0.f; }

    auto ldg_chunk = [&](int g) {
#pragma unroll
        for (int j = 0; j < 2; j++)
            pf[j] = *reinterpret_cast<const float4*>(xsrc + (size_t)j * 32 * DIM + (size_t)g * BKF);
#pragma unroll
        for (int j = 2; j < 10; j++) {
            float4 v = *reinterpret_cast<const float4*>(wsrc + (size_t)(j - 2) * 32 * DIM + (size_t)g * BKF);
            v.x *= WSCALE; v.y *= WSCALE; v.z *= WSCALE; v.w *= WSCALE;   // exact binary scale
            pf[j] = v;
        }
    };

    auto produce = [&](int s) {
        const uint32_t base = sbm + (uint32_t)s * STAGE_B;
#pragma unroll
        for (int j = 0; j < 10; j++) {
            uint32_t addr, tstep;
            if (j < 2) {
                addr = base + (uint32_t)((j * 32 + pr) * STRB + pc * 8);
                tstep = A_T;
            } else {
                addr = base + (uint32_t)(2 * A_T + ((j - 2) * 32 + pr) * STRB + pc * 8);
                tstep = B_T;
            }
            split_store2(pf[j], addr, tstep);
        }
    };

    // prologue
    ldg_chunk(0);
    produce(0);
    __syncthreads();

    for (int g = 0; g < NCHUNK; g++) {
        if (g + 1 < NCHUNK) ldg_chunk(g + 1);

        const uint32_t stg = sbm + (uint32_t)(g & 1) * STAGE_B;
#pragma unroll
        for (int ks = 0; ks < 2; ks++) {
            const uint32_t kb2 = (uint32_t)(ks * 32);
            uint32_t Ah[2][4], Am[2][4];
#pragma unroll
            for (int mt = 0; mt < 2; mt++) {
                const uint32_t a = stg + aBase + (uint32_t)(mt * 16 * STRB) + kb2;
                ldm_x4(Ah[mt], a);
                ldm_x4(Am[mt], a + A_T);
            }
#pragma unroll
            for (int nt2 = 0; nt2 < 4; nt2++) {
                const uint32_t b = stg + bBase + (uint32_t)(nt2 * 16 * STRB) + kb2;
                uint32_t Bh[4], Bm[4];
                ldm_x4(Bh, b);
                ldm_x4(Bm, b + B_T);
#pragma unroll
                for (int half = 0; half < 2; half++) {
                    const int nt = nt2 * 2 + half;
#pragma unroll
                    for (int mt = 0; mt < 2; mt++) {
                        mma_f16(accM[mt][nt], Ah[mt], Bh + half * 2);   // hh (isolated chain)
                        mma_f16(accS[mt][nt], Ah[mt], Bm + half * 2);   // hm
                        mma_f16(accS[mt][nt], Am[mt], Bh + half * 2);   // mh
                        mma_f16(accS[mt][nt], Am[mt], Bm + half * 2);   // mm
                    }
                }
            }
        }

        if (g + 1 < NCHUNK) produce((g + 1) & 1);
        __syncthreads();
    }

    // ---- epilogue: logits (unscaled) into smem [64 x 256], stride LSTR ----
    float* lgs = reinterpret_cast<float*>(smem);
#pragma unroll
    for (int mt = 0; mt < 2; mt++) {
        const int row = wm * 32 + mt * 16 + q;
#pragma unroll
        for (int nt = 0; nt < 8; nt++) {
            const int col = wn * 64 + nt * 8 + t4 * 2;
            float c0 = (accM[mt][nt][0] + accS[mt][nt][0]) * INV_WSCALE;
            float c1 = (accM[mt][nt][1] + accS[mt][nt][1]) * INV_WSCALE;
            float c2 = (accM[mt][nt][2] + accS[mt][nt][2]) * INV_WSCALE;
            float c3 = (accM[mt][nt][3] + accS[mt][nt][3]) * INV_WSCALE;
            *reinterpret_cast<float2*>(&lgs[row * LSTR + col]) = make_float2(c0, c1);
            *reinterpret_cast<float2*>(&lgs[(row + 8) * LSTR + col]) = make_float2(c2, c3);
        }
    }
    __syncthreads();

    // ---- fused routing: each warp routes 8 tokens; lane owns 8 experts ----
    const int ebase = lane * 8;
    const float4 bb0 = *reinterpret_cast<const float4*>(&bias[ebase]);
    const float4 bb1 = *reinterpret_cast<const float4*>(&bias[ebase + 4]);

    for (int it = 0; it < 8; it++) {
        const int tloc = wid * 8 + it;
        const int token = rowBase + tloc;

        float4 l0 = *reinterpret_cast<const float4*>(&lgs[tloc * LSTR + ebase]);
        float4 l1 = *reinterpret_cast<const float4*>(&lgs[tloc * LSTR + ebase + 4]);

        float s[8], sb[8];
        {
            float lv[8] = {l0.x, l0.y, l0.z, l0.w, l1.x, l1.y, l1.z, l1.w};
            float bv[8] = {bb0.x, bb0.y, bb0.z, bb0.w, bb1.x, bb1.y, bb1.z, bb1.w};
#pragma unroll
            for (int j = 0; j < 8; j++) {
                s[j] = 1.0f / (1.0f + expf(-lv[j]));
                sb[j] = s[j] + bv[j];
            }
        }

        // group top-2 (groups of 32 experts = 4 lanes)
        float t1 = -FLT_MAX, t2 = -FLT_MAX;
#pragma unroll
        for (int j = 0; j < 8; j++) {
            if (sb[j] > t1) { t2 = t1; t1 = sb[j]; }
            else if (sb[j] > t2) { t2 = sb[j]; }
        }
#pragma unroll
        for (int off = 1; off < 4; off <<= 1) {
            float o1 = __shfl_xor_sync(0xffffffffu, t1, off);
            float o2 = __shfl_xor_sync(0xffffffffu, t2, off);
            float n1 = fmaxf(t1, o1);
            float n2 = fmaxf(fminf(t1, o1), fmaxf(t2, o2));
            t1 = n1; t2 = n2;
        }
        float gscore = t1 + t2;
        int myg = lane >> 2;

        int rank = 0;
#pragma unroll
        for (int j = 0; j < 8; j++) {
            float gj = __shfl_sync(0xffffffffu, gscore, j * 4);
            rank += (gj > gscore) || (gj == gscore && j < myg);
        }
        bool gsel = rank < TOPKG;

        float v[8];
#pragma unroll
        for (int j = 0; j < 8; j++) v[j] = gsel ? sb[j] : 0.0f;

        int sel_idx = 0;
        float sel_s = 0.0f;
        float ssum = 0.0f;

#pragma unroll
        for (int r = 0; r < TOPK; r++) {
            float bv = -FLT_MAX, bs = 0.0f;
            int bidx = ebase;
#pragma unroll
            for (int j = 0; j < 8; j++) {
                if (v[j] > bv) { bv = v[j]; bidx = ebase + j; bs = s[j]; }
            }
#pragma unroll
            for (int off = 16; off > 0; off >>= 1) {
                float ov = __shfl_xor_sync(0xffffffffu, bv, off);
                int oi = __shfl_xor_sync(0xffffffffu, bidx, off);
                float os = __shfl_xor_sync(0xffffffffu, bs, off);
                if (ov > bv || (ov == bv && oi < bidx)) { bv = ov; bidx = oi; bs = os; }
            }
            if (lane == r) { sel_idx = bidx; sel_s = bs; }
            ssum += bs;
            if (lane == (bidx >> 3)) {
                int slot = bidx & 7;
#pragma unroll
                for (int j = 0; j < 8; j++)
                    if (j == slot) v[j] = -FLT_MAX;
            }
        }

        if (lane < TOPK) {
            float w = sel_s / ssum * ROUTE_SCALE;
            out[(size_t)token * TOPK + lane] = w;
            out[(size_t)TOKENS * TOPK + (size_t)token * TOPK + lane] = (float)sel_idx;
        }
    }
}

extern "C" void kernel_launch(void* const* d_in, const int* in_sizes, int n_in,
                              void* d_out, int out_size) {
    const float* x = (const float*)d_in[0];
    const float* W = (const float*)d_in[1];
    const float* bias = (const float*)d_in[2];
    float* out = (float*)d_out;

    cudaFuncSetAttribute(gate_fused, cudaFuncAttributeMaxDynamicSharedMemorySize, SMEM_TOTAL);
    gate_fused<<<TOKENS / MTILE, 256, SMEM_TOTAL>>>(x, W, bias, out);
}

// round 16
// speedup vs baseline: 1.6173x; 1.2921x over previous
#include <cuda_runtime.h>
#include <cuda_fp16.h>
#include <math.h>
#include <float.h>
#include <stdint.h>

#define TOKENS 8192
#define DIM 4096
#define NEXP 256
#define TOPK 8
#define TOPKG 4
#define ROUTE_SCALE 2.5f
#define WSCALE 64.0f
#define INV_WSCALE 0.015625f

#define MTILE 64
#define BKF 32
#define NCHUNK (DIM / BKF)          // 128
#define STRB 80                     // fp16 tile row stride (bytes)
#define A_T (64 * STRB)             // 5120
#define B_T (256 * STRB)            // 20480
#define STAGE_B (2 * A_T + 2 * B_T) // 51200  (Ah, Am, Bh, Bm)
#define SMEM_TOTAL (2 * STAGE_B)    // 102400
#define LSTR 260                    // logits smem row stride (floats)

// ===================== helpers =====================
__device__ __forceinline__ uint32_t smem_u32(const void* p) {
    uint32_t a;
    asm("{ .reg .u64 t; cvta.to.shared.u64 t, %1; cvt.u32.u64 %0, t; }" : "=r"(a) : "l"(p));
    return a;
}
__device__ __forceinline__ void ldm_x4(uint32_t* r, uint32_t a) {
    asm volatile("ldmatrix.sync.aligned.m8n8.x4.shared.b16 {%0,%1,%2,%3}, [%4];"
        : "=r"(r[0]), "=r"(r[1]), "=r"(r[2]), "=r"(r[3]) : "r"(a));
}
__device__ __forceinline__ void mma_f16(float* c, const uint32_t* a, const uint32_t* b) {
    asm volatile(
        "mma.sync.aligned.m16n8k16.row.col.f32.f16.f16.f32 "
        "{%0,%1,%2,%3}, {%4,%5,%6,%7}, {%8,%9}, {%0,%1,%2,%3};"
        : "+f"(c[0]), "+f"(c[1]), "+f"(c[2]), "+f"(c[3])
        : "r"(a[0]), "r"(a[1]), "r"(a[2]), "r"(a[3]), "r"(b[0]), "r"(b[1]));
}
#define STS64(a, r0, r1) \
    asm volatile("st.shared.v2.b32 [%0], {%1, %2};" :: "r"(a), "r"(r0), "r"(r1) : "memory")

__device__ __forceinline__ uint32_t packh2(__half lo, __half hi) {
    __half2 h = __halves2half2(lo, hi);
    return *reinterpret_cast<uint32_t*>(&h);
}

// fp16 2-way split of one float4 -> store h pair + m pair
__device__ __forceinline__ void split_store2(float4 v, uint32_t addr, uint32_t tstep) {
    __half h0 = __float2half_rn(v.x), h1 = __float2half_rn(v.y);
    __half h2 = __float2half_rn(v.z), h3 = __float2half_rn(v.w);
    float r0 = v.x - __half2float(h0), r1 = v.y - __half2float(h1);
    float r2 = v.z - __half2float(h2), r3 = v.w - __half2float(h3);
    __half m0 = __float2half_rn(r0), m1 = __float2half_rn(r1);
    __half m2 = __float2half_rn(r2), m3 = __float2half_rn(r3);
    STS64(addr, packh2(h0, h1), packh2(h2, h3));
    STS64(addr + tstep, packh2(m0, m1), packh2(m2, m3));
}

// ===================== fused kernel: GEMM(fp16x2, 4 terms) + routing =====================
__global__ __launch_bounds__(256, 1)
void gate_fused(const float* __restrict__ x, const float* __restrict__ W,
                const float* __restrict__ bias, float* __restrict__ out) {
    extern __shared__ char smem[];
    const uint32_t sbm = smem_u32(smem);

    const int tid = threadIdx.x;
    const int wid = tid >> 5;
    const int lane = tid & 31;
    const int q = lane >> 2;
    const int t4 = lane & 3;
    const int wm = wid & 1;          // token half: rows wm*32
    const int wn = wid >> 1;         // expert quarter: cols wn*64
    const int rowBase = blockIdx.x * MTILE;

    // ---- producer mapping: 10 x float4 per thread per chunk (2 A, 8 B) ----
    const int pr = tid >> 3;         // 0..31 row-in-group
    const int pc = tid & 7;          // 16B segment
    const float* xsrc = x + (size_t)(rowBase + pr) * DIM + pc * 4;
    const float* wsrc = W + (size_t)pr * DIM + pc * 4;
    float4 pf[10];

    // ---- consumer ldmatrix bases ----
    const uint32_t aBase = (uint32_t)((wm * 32 + ((lane >> 3) & 1) * 8 + (lane & 7)) * STRB
                                      + (lane >> 4) * 16);
    const uint32_t bBase = (uint32_t)(2 * A_T
                                      + (wn * 64 + (lane & 7) + (lane >> 4) * 8) * STRB
                                      + ((lane >> 3) & 1) * 16);

    float accM[2][8][4];
    float accS[2][8][4];
#pragma unroll
    for (int mt = 0; mt < 2; mt++)
#pragma unroll
        for (int nt = 0; nt < 8; nt++)
#pragma unroll
            for (int e = 0; e < 4; e++) { accM[mt][nt][e] = 0.f; accS[mt][nt][e] = 0.f; }

    auto ldg_chunk = [&](int g) {
#pragma unroll
        for (int j = 0; j < 2; j++)
            pf[j] = *reinterpret_cast<const float4*>(xsrc + (size_t)j * 32 * DIM + (size_t)g * BKF);
#pragma unroll
        for (int j = 2; j < 10; j++) {
            float4 v = *reinterpret_cast<const float4*>(wsrc + (size_t)(j - 2) * 32 * DIM + (size_t)g * BKF);
            v.x *= WSCALE; v.y *= WSCALE; v.z *= WSCALE; v.w *= WSCALE;   // exact binary scale
            pf[j] = v;
        }
    };

    // split_store for pf[j] into write-stage base (compile-time j folds the if)
    const uint32_t addrA = (uint32_t)(pr * STRB + pc * 8);
    const uint32_t addrB = (uint32_t)(2 * A_T + pr * STRB + pc * 8);

    // prologue: produce chunk 0 into stage 0
    ldg_chunk(0);
    {
        const uint32_t base = sbm;
#pragma unroll
        for (int j = 0; j < 2; j++)
            split_store2(pf[j], base + addrA + (uint32_t)(j * 32 * STRB), A_T);
#pragma unroll
        for (int j = 2; j < 10; j++)
            split_store2(pf[j], base + addrB + (uint32_t)((j - 2) * 32 * STRB), B_T);
    }
    __syncthreads();

    for (int g = 0; g < NCHUNK; g++) {
        // prefetch chunk g+1 (clamped; last iteration reloads chunk NCHUNK-1 harmlessly)
        const int gn = (g + 1 < NCHUNK) ? (g + 1) : (NCHUNK - 1);
        ldg_chunk(gn);

        const uint32_t stg = sbm + (uint32_t)(g & 1) * STAGE_B;          // read stage
        const uint32_t wstg = sbm + (uint32_t)((g + 1) & 1) * STAGE_B;   // write stage

#pragma unroll
        for (int ks = 0; ks < 2; ks++) {
            const uint32_t kb2 = (uint32_t)(ks * 32);
            uint32_t Ah[2][4], Am[2][4];
#pragma unroll
            for (int mt = 0; mt < 2; mt++) {
                const uint32_t a = stg + aBase + (uint32_t)(mt * 16 * STRB) + kb2;
                ldm_x4(Ah[mt], a);
                ldm_x4(Am[mt], a + A_T);
            }
#pragma unroll
            for (int nt2 = 0; nt2 < 4; nt2++) {
                const uint32_t b = stg + bBase + (uint32_t)(nt2 * 16 * STRB) + kb2;
                uint32_t Bh[4], Bm[4];
                ldm_x4(Bh, b);
                ldm_x4(Bm, b + B_T);
#pragma unroll
                for (int half = 0; half < 2; half++) {
                    const int nt = nt2 * 2 + half;
#pragma unroll
                    for (int mt = 0; mt < 2; mt++) {
                        mma_f16(accM[mt][nt], Ah[mt], Bh + half * 2);   // hh (isolated chain)
                        mma_f16(accS[mt][nt], Ah[mt], Bm + half * 2);   // hm
                        mma_f16(accS[mt][nt], Am[mt], Bh + half * 2);   // mh
                        mma_f16(accS[mt][nt], Am[mt], Bm + half * 2);   // mm
                    }
                }
                // ---- interleaved produce for chunk g+1 (ks==1 only):
                // split/STS issue in the tensor pipe's idle issue slots.
                if (ks == 1) {
                    switch (nt2) {
                        case 0:
                            split_store2(pf[0], wstg + addrA, A_T);
                            split_store2(pf[1], wstg + addrA + (uint32_t)(32 * STRB), A_T);
                            split_store2(pf[2], wstg + addrB, B_T);
                            break;
                        case 1:
                            split_store2(pf[3], wstg + addrB + (uint32_t)(32 * STRB), B_T);
                            split_store2(pf[4], wstg + addrB + (uint32_t)(64 * STRB), B_T);
                            break;
                        case 2:
                            split_store2(pf[5], wstg + addrB + (uint32_t)(96 * STRB), B_T);
                            split_store2(pf[6], wstg + addrB + (uint32_t)(128 * STRB), B_T);
                            break;
                        case 3:
                            split_store2(pf[7], wstg + addrB + (uint32_t)(160 * STRB), B_T);
                            split_store2(pf[8], wstg + addrB + (uint32_t)(192 * STRB), B_T);
                            split_store2(pf[9], wstg + addrB + (uint32_t)(224 * STRB), B_T);
                            break;
                    }
                }
            }
        }
        __syncthreads();
    }

    // ---- epilogue: logits into smem [64 x 256], stride LSTR ----
    float* lgs = reinterpret_cast<float*>(smem);
#pragma unroll
    for (int mt = 0; mt < 2; mt++) {
        const int row = wm * 32 + mt * 16 + q;
#pragma unroll
        for (int nt = 0; nt < 8; nt++) {
            const int col = wn * 64 + nt * 8 + t4 * 2;
            float c0 = (accM[mt][nt][0] + accS[mt][nt][0]) * INV_WSCALE;
            float c1 = (accM[mt][nt][1] + accS[mt][nt][1]) * INV_WSCALE;
            float c2 = (accM[mt][nt][2] + accS[mt][nt][2]) * INV_WSCALE;
            float c3 = (accM[mt][nt][3] + accS[mt][nt][3]) * INV_WSCALE;
            *reinterpret_cast<float2*>(&lgs[row * LSTR + col]) = make_float2(c0, c1);
            *reinterpret_cast<float2*>(&lgs[(row + 8) * LSTR + col]) = make_float2(c2, c3);
        }
    }
    __syncthreads();

    // ---- fused routing: each warp routes 8 tokens; lane owns 8 experts ----
    const int ebase = lane * 8;
    const float4 bb0 = *reinterpret_cast<const float4*>(&bias[ebase]);
    const float4 bb1 = *reinterpret_cast<const float4*>(&bias[ebase + 4]);

    for (int it = 0; it < 8; it++) {
        const int tloc = wid * 8 + it;
        const int token = rowBase + tloc;

        float4 l0 = *reinterpret_cast<const float4*>(&lgs[tloc * LSTR + ebase]);
        float4 l1 = *reinterpret_cast<const float4*>(&lgs[tloc * LSTR + ebase + 4]);

        float s[8], sb[8];
        {
            float lv[8] = {l0.x, l0.y, l0.z, l0.w, l1.x, l1.y, l1.z, l1.w};
            float bv[8] = {bb0.x, bb0.y, bb0.z, bb0.w, bb1.x, bb1.y, bb1.z, bb1.w};
#pragma unroll
            for (int j = 0; j < 8; j++) {
                s[j] = 1.0f / (1.0f + expf(-lv[j]));
                sb[j] = s[j] + bv[j];
            }
        }

        float t1 = -FLT_MAX, t2 = -FLT_MAX;
#pragma unroll
        for (int j = 0; j < 8; j++) {
            if (sb[j] > t1) { t2 = t1; t1 = sb[j]; }
            else if (sb[j] > t2) { t2 = sb[j]; }
        }
#pragma unroll
        for (int off = 1; off < 4; off <<= 1) {
            float o1 = __shfl_xor_sync(0xffffffffu, t1, off);
            float o2 = __shfl_xor_sync(0xffffffffu, t2, off);
            float n1 = fmaxf(t1, o1);
            float n2 = fmaxf(fminf(t1, o1), fmaxf(t2, o2));
            t1 = n1; t2 = n2;
        }
        float gscore = t1 + t2;
        int myg = lane >> 2;

        int rank = 0;
#pragma unroll
        for (int j = 0; j < 8; j++) {
            float gj = __shfl_sync(0xffffffffu, gscore, j * 4);
            rank += (gj > gscore) || (gj == gscore && j < myg);
        }
        bool gsel = rank < TOPKG;

        float v[8];
#pragma unroll
        for (int j = 0; j < 8; j++) v[j] = gsel ? sb[j] : 0.0f;

        int sel_idx = 0;
        float sel_s = 0.0f;
        float ssum = 0.0f;

#pragma unroll
        for (int r = 0; r < TOPK; r++) {
            float bv = -FLT_MAX, bs = 0.0f;
            int bidx = ebase;
#pragma unroll
            for (int j = 0; j < 8; j++) {
                if (v[j] > bv) { bv = v[j]; bidx = ebase + j; bs = s[j]; }
            }
#pragma unroll
            for (int off = 16; off > 0; off >>= 1) {
                float ov = __shfl_xor_sync(0xffffffffu, bv, off);
                int oi = __shfl_xor_sync(0xffffffffu, bidx, off);
                float os = __shfl_xor_sync(0xffffffffu, bs, off);
                if (ov > bv || (ov == bv && oi < bidx)) { bv = ov; bidx = oi; bs = os; }
            }
            if (lane == r) { sel_idx = bidx; sel_s = bs; }
            ssum += bs;
            if (lane == (bidx >> 3)) {
                int slot = bidx & 7;
#pragma unroll
                for (int j = 0; j < 8; j++)
                    if (j == slot) v[j] = -FLT_MAX;
            }
        }

        if (lane < TOPK) {
            float w = sel_s / ssum * ROUTE_SCALE;
            out[(size_t)token * TOPK + lane] = w;
            out[(size_t)TOKENS * TOPK + (size_t)token * TOPK + lane] = (float)sel_idx;
        }
    }
}

extern "C" void kernel_launch(void* const* d_in, const int* in_sizes, int n_in,
                              void* d_out, int out_size) {
    const float* x = (const float*)d_in[0];
    const float* W = (const float*)d_in[1];
    const float* bias = (const float*)d_in[2];
    float* out = (float*)d_out;

    cudaFuncSetAttribute(gate_fused, cudaFuncAttributeMaxDynamicSharedMemorySize, SMEM_TOTAL);
    gate_fused<<<TOKENS / MTILE, 256, SMEM_TOTAL>>>(x, W, bias, out);
}